// round 1
// baseline (speedup 1.0000x reference)
#include <cuda_runtime.h>
#include <math.h>

// Piecewise-quadratic 1/sqrt(x) evaluation.
// Segment selection: fast bit-trick log2 estimate (error < 0.07 segments),
// then one exact compare vs breaks[s0] (via warp shuffle) to reproduce
// jnp.searchsorted(breaks, x, side='left') - 1 semantics bit-exactly.
// Coefficients are fetched from registers via warp shuffles (no smem, no LDG
// per element), keeping per-element cost ~17 instructions -> HBM-bound.

__device__ float g_K1, g_K2;

__global__ void pw_setup_kernel(const float* __restrict__ breaks, int nseg) {
    // single thread: derive the bit-trick constants from the actual breaks.
    double lo = (double)breaks[0];
    double hi = (double)breaks[nseg];
    double K  = (double)nseg / (log2(hi) - log2(lo));
    // max of log2(1+m)-m is 0.0860713; center the error with sigma = half.
    const double sigma = 0.04303565;
    g_K1 = (float)(K * (1.0 / 8388608.0)); // K * 2^-23
    g_K2 = (float)(K * (-127.0 + sigma - log2(lo)) + 0.5);
}

__device__ __forceinline__ float pw_eval(float x, float K1, float K2,
                                         float brk, float ca, float cb, float cc,
                                         int segmax) {
    // t ~= K*log2(x/LO) + 0.5, error in [-0.065, +0.065]
    float tf = (float)__float_as_int(x);
    float t  = fmaf(tf, K1, K2);
    int s0 = (int)t;                         // true seg is s0-1 or s0
    s0 = max(0, min(s0, segmax + 1));        // safety clamp for out-of-spec x
    float bmid = __shfl_sync(0xffffffffu, brk, s0);
    int s = s0 - 1 + (x > bmid ? 1 : 0);     // strict '>' == searchsorted left
    s = max(s, 0);
    s = min(s, segmax);
    float a = __shfl_sync(0xffffffffu, ca, s);
    float b = __shfl_sync(0xffffffffu, cb, s);
    float c = __shfl_sync(0xffffffffu, cc, s);
    return fmaf(fmaf(a, x, b), x, c);
}

__global__ void __launch_bounds__(256)
pw_main_kernel(const float* __restrict__ x,
               const float* __restrict__ breaks,
               const float* __restrict__ coeffs,
               float* __restrict__ y,
               int n, int nseg) {
    const int lane = threadIdx.x & 31;

    // Per-warp register tables: breaks in lanes 0..nseg, coeffs in lanes 0..nseg-1
    float brk = __int_as_float(0x7f800000);  // +inf in unused lanes
    if (lane <= nseg) brk = __ldg(breaks + lane);
    float ca = 0.0f, cb = 0.0f, cc = 0.0f;
    if (lane < nseg) {
        ca = __ldg(coeffs + 3 * lane + 0);
        cb = __ldg(coeffs + 3 * lane + 1);
        cc = __ldg(coeffs + 3 * lane + 2);
    }
    const float K1 = g_K1;
    const float K2 = g_K2;
    const int segmax = nseg - 1;

    const int n4 = n >> 2;
    const float4* __restrict__ x4 = (const float4*)x;
    float4*       __restrict__ y4 = (float4*)y;

    const int tid    = blockIdx.x * blockDim.x + threadIdx.x;
    const int stride = gridDim.x * blockDim.x;

    // Vectorized main loop. Loop condition is warp-uniform (warp base index),
    // so every __shfl_sync executes with all 32 lanes present; only the store
    // is guarded.
    for (int i = tid; (i - lane) < n4; i += stride) {
        int j = (i < n4) ? i : (n4 - 1);
        float4 v = __ldcs(x4 + j);           // streaming load (no reuse)
        float4 r;
        r.x = pw_eval(v.x, K1, K2, brk, ca, cb, cc, segmax);
        r.y = pw_eval(v.y, K1, K2, brk, ca, cb, cc, segmax);
        r.z = pw_eval(v.z, K1, K2, brk, ca, cb, cc, segmax);
        r.w = pw_eval(v.w, K1, K2, brk, ca, cb, cc, segmax);
        if (i < n4) __stcs(y4 + j, r);
    }

    // Scalar tail (n % 4 != 0), same warp-safe pattern.
    const int base = n4 << 2;
    for (int i = base + tid; (i - lane) < n; i += stride) {
        int j = (i < n) ? i : (n - 1);
        float v = __ldg(x + j);
        float r = pw_eval(v, K1, K2, brk, ca, cb, cc, segmax);
        if (i < n) y[j] = r;
    }
}

extern "C" void kernel_launch(void* const* d_in, const int* in_sizes, int n_in,
                              void* d_out, int out_size) {
    const float* x      = (const float*)d_in[0];
    const float* breaks = (const float*)d_in[1];
    const float* coeffs = (const float*)d_in[2];
    float*       y      = (float*)d_out;

    const int n    = in_sizes[0];
    const int nseg = in_sizes[2] / 3;   // coeffs is [nseg, 3]

    pw_setup_kernel<<<1, 1>>>(breaks, nseg);

    const int n4   = n >> 2;
    const int work = (n4 > 0) ? n4 : n;
    int blocks = (work + 255) / 256;
    if (blocks > 4736) blocks = 4736;   // 32 blocks/SM worth of grid-stride work
    if (blocks < 1)    blocks = 1;
    pw_main_kernel<<<blocks, 256>>>(x, breaks, coeffs, y, n, nseg);
}